// round 3
// baseline (speedup 1.0000x reference)
#include <cuda_runtime.h>
#include <cstdint>

#define N_NODES 100000
#define N_EDGES 3200000
#define N_FEAT  512
#define N_HID   256

// ---------------- static scratch (no allocation allowed) ----------------
__device__ float d_h[(size_t)N_NODES * N_HID];     // FC output
__device__ float d_g[(size_t)N_NODES * N_HID];     // post-SpMM/PReLU
__device__ int   d_rowptr[N_NODES + 1];
__device__ int   d_cursor[N_NODES];
__device__ int   d_colidx[N_EDGES];
__device__ float d_eval[N_EDGES];
__device__ int   d_bsum[128];
__device__ float d_colsum[N_HID];
__device__ float d_v[N_HID];
__device__ int   d_is32;                           // edge_index stored as int32?

// ---------------- helpers ----------------
__device__ __forceinline__ float tf32r(float x) {
    uint32_t u;
    asm("cvt.rna.tf32.f32 %0, %1;" : "=r"(u) : "f"(x));
    return __uint_as_float(u);
}

__device__ __forceinline__ void mma1688(float* c, const uint32_t* a, const uint32_t* b) {
    asm volatile(
        "mma.sync.aligned.m16n8k8.row.col.f32.tf32.tf32.f32 "
        "{%0,%1,%2,%3}, {%4,%5,%6,%7}, {%8,%9}, {%0,%1,%2,%3};"
        : "+f"(c[0]), "+f"(c[1]), "+f"(c[2]), "+f"(c[3])
        : "r"(a[0]), "r"(a[1]), "r"(a[2]), "r"(a[3]), "r"(b[0]), "r"(b[1]));
}

__device__ __forceinline__ int warp_incl_scan(int v) {
    int lane = threadIdx.x & 31;
#pragma unroll
    for (int o = 1; o < 32; o <<= 1) {
        int t = __shfl_up_sync(0xffffffffu, v, o);
        if (lane >= o) v += t;
    }
    return v;
}

__device__ __forceinline__ int block_incl_scan(int v, int* smem) {
    int lane = threadIdx.x & 31;
    int wid  = threadIdx.x >> 5;
    int nw   = blockDim.x >> 5;
    int s = warp_incl_scan(v);
    if (lane == 31) smem[wid] = s;
    __syncthreads();
    if (wid == 0) {
        int t = (lane < nw) ? smem[lane] : 0;
        t = warp_incl_scan(t);
        if (lane < nw) smem[lane] = t;
    }
    __syncthreads();
    int add = (wid > 0) ? smem[wid - 1] : 0;
    return s + add;
}

__device__ __forceinline__ int edge_at(const void* eidx, size_t idx) {
    if (d_is32) return ((const int*)eidx)[idx];
    return (int)((const long long*)eidx)[idx];
}

// ---------------- dtype detection (device-side, graph-capturable) ----------------
__global__ void detect_kernel(const void* eidx) {
    if (threadIdx.x == 0 && blockIdx.x == 0) {
        const long long* p = (const long long*)eidx;
        int is32 = 0;
        for (int i = 0; i < 64; i++) {
            long long v = p[i];
            if (v < 0 || v >= (long long)N_NODES) { is32 = 1; break; }
        }
        d_is32 = is32;
    }
}

// ---------------- graph build ----------------
__global__ void zero_kernel() {
    int i = blockIdx.x * blockDim.x + threadIdx.x;
    if (i < N_NODES) d_cursor[i] = 0;
    if (i < N_HID)   d_colsum[i] = 0.f;
}

__global__ void hist_kernel(const void* __restrict__ eidx) {
    int e = blockIdx.x * blockDim.x + threadIdx.x;
    if (e < N_EDGES) {
        int r = edge_at(eidx, (size_t)e);
        if ((unsigned)r < (unsigned)N_NODES)
            atomicAdd(&d_cursor[r], 1);
    }
}

__global__ void scan1_kernel() {
    __shared__ int smem[32];
    int i = blockIdx.x * 1024 + threadIdx.x;
    int c = (i < N_NODES) ? d_cursor[i] : 0;
    int s = block_incl_scan(c, smem);
    if (threadIdx.x == 1023) d_bsum[blockIdx.x] = s;
}

__global__ void scan2_kernel(int nblocks) {
    __shared__ int smem[32];
    int t = threadIdx.x;
    int v = (t < nblocks) ? d_bsum[t] : 0;
    int s = block_incl_scan(v, smem);
    if (t < nblocks) d_bsum[t] = s - v;  // exclusive
}

__global__ void scan3_kernel() {
    __shared__ int smem[32];
    int i = blockIdx.x * 1024 + threadIdx.x;
    int c = (i < N_NODES) ? d_cursor[i] : 0;
    int s = block_incl_scan(c, smem);
    int base = d_bsum[blockIdx.x];
    if (i < N_NODES) {
        int end = base + s;
        d_rowptr[i + 1] = end;
        d_cursor[i] = end - c;   // segment start; used as scatter cursor
    }
    if (i == 0) d_rowptr[0] = 0;
}

__global__ void scatter_kernel(const void* __restrict__ eidx,
                               const float* __restrict__ evals) {
    int e = blockIdx.x * blockDim.x + threadIdx.x;
    if (e < N_EDGES) {
        int r = edge_at(eidx, (size_t)e);
        int c = edge_at(eidx, (size_t)N_EDGES + e);
        if ((unsigned)r >= (unsigned)N_NODES) return;
        if ((unsigned)c >= (unsigned)N_NODES) c = 0;
        int p = atomicAdd(&d_cursor[r], 1);
        if ((unsigned)p < (unsigned)N_EDGES) {
            d_colidx[p] = c;
            d_eval[p]   = evals[e];
        }
    }
}

// ---------------- GEMM (3xTF32 tensor core) ----------------
// H[m,n] = sum_k X[m,k] * W[n,k] + b[n]
// BM=128, BN=64, BK=16; 256 threads; warp tile 32x32 (warp grid 4x2)
__global__ __launch_bounds__(256, 2)
void gemm_tf32_kernel(const float* __restrict__ A, const float* __restrict__ W,
                      const float* __restrict__ bias) {
    __shared__ float sAh[16][132];
    __shared__ float sAl[16][132];
    __shared__ float sBh[16][68];
    __shared__ float sBl[16][68];

    const int tid  = threadIdx.x;
    const int lane = tid & 31;
    const int wid  = tid >> 5;
    const int m0 = blockIdx.y * 128;
    const int n0 = blockIdx.x * 64;
    const int wm = (wid >> 1) * 32;   // warp m offset within block: 0/32/64/96
    const int wn = (wid & 1) * 32;    // warp n offset within block: 0/32
    const int gp = lane >> 2;         // group id (0..7)
    const int tg = lane & 3;          // thread in group (0..3)

    float acc[2][4][4];
#pragma unroll
    for (int mi = 0; mi < 2; mi++)
#pragma unroll
        for (int nj = 0; nj < 4; nj++)
#pragma unroll
            for (int c = 0; c < 4; c++) acc[mi][nj][c] = 0.f;

    // global load mapping
    const int am0 = tid >> 2;                 // 0..63
    const int ak0 = (tid & 3) * 4;
    const int am1 = am0 + 64;                 // 64..127
    const int ak1 = ak0;
    int ar0 = m0 + am0; if (ar0 > N_NODES - 1) ar0 = N_NODES - 1;
    int ar1 = m0 + am1; if (ar1 > N_NODES - 1) ar1 = N_NODES - 1;
    const float* ap0 = A + (size_t)ar0 * N_FEAT + ak0;
    const float* ap1 = A + (size_t)ar1 * N_FEAT + ak1;
    const int bn = tid >> 2;                  // 0..63
    const int bk = (tid & 3) * 4;
    const float* bp = W + (size_t)(n0 + bn) * N_FEAT + bk;

    for (int k0 = 0; k0 < N_FEAT; k0 += 16) {
        float4 va0 = *(const float4*)(ap0 + k0);
        float4 va1 = *(const float4*)(ap1 + k0);
        float4 vb  = *(const float4*)(bp + k0);
        __syncthreads();
        {
            float f0[4] = {va0.x, va0.y, va0.z, va0.w};
            float f1[4] = {va1.x, va1.y, va1.z, va1.w};
            float fb[4] = {vb.x,  vb.y,  vb.z,  vb.w};
#pragma unroll
            for (int j = 0; j < 4; j++) {
                float h0 = tf32r(f0[j]);
                sAh[ak0 + j][am0] = h0;
                sAl[ak0 + j][am0] = tf32r(f0[j] - h0);
                float h1 = tf32r(f1[j]);
                sAh[ak1 + j][am1] = h1;
                sAl[ak1 + j][am1] = tf32r(f1[j] - h1);
                float hb = tf32r(fb[j]);
                sBh[bk + j][bn] = hb;
                sBl[bk + j][bn] = tf32r(fb[j] - hb);
            }
        }
        __syncthreads();
#pragma unroll
        for (int ks = 0; ks < 16; ks += 8) {
            uint32_t ah[2][4], al[2][4], bh[4][2], bl[4][2];
#pragma unroll
            for (int mi = 0; mi < 2; mi++) {
                int mr = wm + mi * 16 + gp;
                ah[mi][0] = __float_as_uint(sAh[ks + tg][mr]);
                ah[mi][1] = __float_as_uint(sAh[ks + tg][mr + 8]);
                ah[mi][2] = __float_as_uint(sAh[ks + 4 + tg][mr]);
                ah[mi][3] = __float_as_uint(sAh[ks + 4 + tg][mr + 8]);
                al[mi][0] = __float_as_uint(sAl[ks + tg][mr]);
                al[mi][1] = __float_as_uint(sAl[ks + tg][mr + 8]);
                al[mi][2] = __float_as_uint(sAl[ks + 4 + tg][mr]);
                al[mi][3] = __float_as_uint(sAl[ks + 4 + tg][mr + 8]);
            }
#pragma unroll
            for (int nj = 0; nj < 4; nj++) {
                int nc = wn + nj * 8 + gp;
                bh[nj][0] = __float_as_uint(sBh[ks + tg][nc]);
                bh[nj][1] = __float_as_uint(sBh[ks + 4 + tg][nc]);
                bl[nj][0] = __float_as_uint(sBl[ks + tg][nc]);
                bl[nj][1] = __float_as_uint(sBl[ks + 4 + tg][nc]);
            }
#pragma unroll
            for (int mi = 0; mi < 2; mi++)
#pragma unroll
                for (int nj = 0; nj < 4; nj++) {
                    mma1688(acc[mi][nj], ah[mi], bh[nj]);
                    mma1688(acc[mi][nj], al[mi], bh[nj]);
                    mma1688(acc[mi][nj], ah[mi], bl[nj]);
                }
        }
    }

    // epilogue: c0/c1 -> (row, col..col+1), c2/c3 -> (row+8, col..col+1)
#pragma unroll
    for (int mi = 0; mi < 2; mi++) {
        int r0 = m0 + wm + mi * 16 + gp;
        int r1 = r0 + 8;
#pragma unroll
        for (int nj = 0; nj < 4; nj++) {
            int col = n0 + wn + nj * 8 + tg * 2;
            float b0 = bias[col], b1 = bias[col + 1];
            if (r0 < N_NODES) {
                float2 o = make_float2(acc[mi][nj][0] + b0, acc[mi][nj][1] + b1);
                *(float2*)&d_h[(size_t)r0 * N_HID + col] = o;
            }
            if (r1 < N_NODES) {
                float2 o = make_float2(acc[mi][nj][2] + b0, acc[mi][nj][3] + b1);
                *(float2*)&d_h[(size_t)r1 * N_HID + col] = o;
            }
        }
    }
}

// ---------------- SpMM + PReLU: g[n,:] = prelu(sum_e w_e * h[col_e,:]) ----------------
__global__ __launch_bounds__(256)
void spmm_kernel(const float* __restrict__ prelu_a) {
    const int node = blockIdx.x;
    const int j = threadIdx.x;
    const int beg = d_rowptr[node];
    const int end = d_rowptr[node + 1];
    float acc = 0.f;
    int e = beg;
    for (; e + 4 <= end; e += 4) {
        int c0 = d_colidx[e], c1 = d_colidx[e + 1];
        int c2 = d_colidx[e + 2], c3 = d_colidx[e + 3];
        float w0 = d_eval[e], w1 = d_eval[e + 1];
        float w2 = d_eval[e + 2], w3 = d_eval[e + 3];
        float v0 = d_h[(size_t)c0 * N_HID + j];
        float v1 = d_h[(size_t)c1 * N_HID + j];
        float v2 = d_h[(size_t)c2 * N_HID + j];
        float v3 = d_h[(size_t)c3 * N_HID + j];
        acc += w0 * v0; acc += w1 * v1; acc += w2 * v2; acc += w3 * v3;
    }
    for (; e < end; ++e)
        acc += d_eval[e] * d_h[(size_t)d_colidx[e] * N_HID + j];
    float a0 = prelu_a[0];
    acc = (acc >= 0.f) ? acc : a0 * acc;
    d_g[(size_t)node * N_HID + j] = acc;
}

// ---------------- column sum of g (for mean over nodes) ----------------
__global__ void colsum_kernel() {
    const int j = threadIdx.x;
    const int start = blockIdx.x * 512;
    int stop = start + 512;
    if (stop > N_NODES) stop = N_NODES;
    float s = 0.f;
    for (int n = start; n < stop; n++) s += d_g[(size_t)n * N_HID + j];
    atomicAdd(&d_colsum[j], s);
}

// ---------------- v = bil_w @ sigmoid(mean) ----------------
__global__ void vker(const float* __restrict__ bw) {
    __shared__ float ssig[N_HID];
    int t = threadIdx.x;
    ssig[t] = 1.f / (1.f + expf(-d_colsum[t] * (1.f / (float)N_NODES)));
    __syncthreads();
    float acc = 0.f;
#pragma unroll 8
    for (int g = 0; g < N_HID; g++) acc += bw[t * N_HID + g] * ssig[g];
    d_v[t] = acc;
}

// ---------------- score[n] = dot(g[n], v) + bil_b ----------------
__global__ __launch_bounds__(256)
void score_kernel(const float* __restrict__ bb, float* __restrict__ out) {
    const int warp = threadIdx.x >> 5;
    const int lane = threadIdx.x & 31;
    const int node = blockIdx.x * 8 + warp;
    if (node >= N_NODES) return;
    const float4* gr = (const float4*)&d_g[(size_t)node * N_HID];
    const float4* vv = (const float4*)d_v;
    float acc = 0.f;
#pragma unroll
    for (int i = lane; i < 64; i += 32) {
        float4 a = gr[i];
        float4 b = vv[i];
        acc += a.x * b.x + a.y * b.y + a.z * b.z + a.w * b.w;
    }
#pragma unroll
    for (int o = 16; o > 0; o >>= 1) acc += __shfl_xor_sync(0xffffffffu, acc, o);
    if (lane == 0) out[node] = acc + bb[0];
}

// ---------------- launch ----------------
extern "C" void kernel_launch(void* const* d_in, const int* in_sizes, int n_in,
                              void* d_out, int out_size) {
    const float* x1  = (const float*)d_in[0];
    const float* x2  = (const float*)d_in[1];
    const float* ev  = (const float*)d_in[2];
    const float* fcw = (const float*)d_in[3];
    const float* fcb = (const float*)d_in[4];
    const float* pa  = (const float*)d_in[5];
    const float* bw  = (const float*)d_in[6];
    const float* bb  = (const float*)d_in[7];
    const void*  ei  = (const void*)d_in[8];
    float* out = (float*)d_out;

    const int scan_blocks = (N_NODES + 1023) / 1024;   // 98
    const int edge_blocks = (N_EDGES + 255) / 256;     // 12500

    // CSR build (per call; part of timed work)
    detect_kernel<<<1, 32>>>(ei);
    zero_kernel<<<(N_NODES + 255) / 256, 256>>>();
    hist_kernel<<<edge_blocks, 256>>>(ei);
    scan1_kernel<<<scan_blocks, 1024>>>();
    scan2_kernel<<<1, 128>>>(scan_blocks);
    scan3_kernel<<<scan_blocks, 1024>>>();
    scatter_kernel<<<edge_blocks, 256>>>(ei, ev);

    dim3 ggrid(N_HID / 64, (N_NODES + 127) / 128);   // (4, 782)

    // graph 1
    gemm_tf32_kernel<<<ggrid, 256>>>(x1, fcw, fcb);
    spmm_kernel<<<N_NODES, 256>>>(pa);
    colsum_kernel<<<(N_NODES + 511) / 512, 256>>>();
    vker<<<1, N_HID>>>(bw);
    score_kernel<<<(N_NODES + 7) / 8, 256>>>(bb, out);

    // graph 2 (reuses d_h/d_g; v already fixed)
    gemm_tf32_kernel<<<ggrid, 256>>>(x2, fcw, fcb);
    spmm_kernel<<<N_NODES, 256>>>(pa);
    score_kernel<<<(N_NODES + 7) / 8, 256>>>(bb, out + N_NODES);
}

// round 5
// speedup vs baseline: 1.5896x; 1.5896x over previous
#include <cuda_runtime.h>
#include <cstdint>

#define N_NODES 100000
#define N_EDGES 3200000
#define N_FEAT  512
#define N_HID   256

// ---------------- static scratch (no allocation allowed) ----------------
__device__ float d_h[(size_t)N_NODES * N_HID];     // FC output
__device__ float d_g[(size_t)N_NODES * N_HID];     // post-SpMM/PReLU
__device__ int   d_rowptr[N_NODES + 1];
__device__ int   d_cursor[N_NODES];
__device__ int   d_colidx[N_EDGES];
__device__ float d_eval[N_EDGES];
__device__ int   d_bsum[128];
__device__ float d_colsum[N_HID];
__device__ float d_v[N_HID];
__device__ int   d_is32;                           // edge_index stored as int32?

// ---------------- helpers ----------------
typedef unsigned long long u64;

__device__ __forceinline__ void fma2(u64& c, u64 a, u64 b) {
    asm("fma.rn.f32x2 %0, %1, %2, %0;" : "+l"(c) : "l"(a), "l"(b));
}
__device__ __forceinline__ u64 splat2(float a) {
    u64 r; asm("mov.b64 %0, {%1, %1};" : "=l"(r) : "f"(a)); return r;
}
__device__ __forceinline__ float2 unpack2(u64 v) {
    float2 r; asm("mov.b64 {%0, %1}, %2;" : "=f"(r.x), "=f"(r.y) : "l"(v)); return r;
}

__device__ __forceinline__ int warp_incl_scan(int v) {
    int lane = threadIdx.x & 31;
#pragma unroll
    for (int o = 1; o < 32; o <<= 1) {
        int t = __shfl_up_sync(0xffffffffu, v, o);
        if (lane >= o) v += t;
    }
    return v;
}

__device__ __forceinline__ int block_incl_scan(int v, int* smem) {
    int lane = threadIdx.x & 31;
    int wid  = threadIdx.x >> 5;
    int nw   = blockDim.x >> 5;
    int s = warp_incl_scan(v);
    if (lane == 31) smem[wid] = s;
    __syncthreads();
    if (wid == 0) {
        int t = (lane < nw) ? smem[lane] : 0;
        t = warp_incl_scan(t);
        if (lane < nw) smem[lane] = t;
    }
    __syncthreads();
    int add = (wid > 0) ? smem[wid - 1] : 0;
    return s + add;
}

__device__ __forceinline__ int edge_at(const void* eidx, size_t idx) {
    if (d_is32) return ((const int*)eidx)[idx];
    return (int)((const long long*)eidx)[idx];
}

// ---------------- dtype detection (device-side, graph-capturable) ----------------
__global__ void detect_kernel(const void* eidx) {
    if (threadIdx.x == 0 && blockIdx.x == 0) {
        const long long* p = (const long long*)eidx;
        int is32 = 0;
        for (int i = 0; i < 64; i++) {
            long long v = p[i];
            if (v < 0 || v >= (long long)N_NODES) { is32 = 1; break; }
        }
        d_is32 = is32;
    }
}

// ---------------- graph build ----------------
__global__ void zero_kernel() {
    int i = blockIdx.x * blockDim.x + threadIdx.x;
    if (i < N_NODES) d_cursor[i] = 0;
    if (i < N_HID)   d_colsum[i] = 0.f;
}

__global__ void hist_kernel(const void* __restrict__ eidx) {
    int e = blockIdx.x * blockDim.x + threadIdx.x;
    if (e < N_EDGES) {
        int r = edge_at(eidx, (size_t)e);
        if ((unsigned)r < (unsigned)N_NODES)
            atomicAdd(&d_cursor[r], 1);
    }
}

__global__ void scan1_kernel() {
    __shared__ int smem[32];
    int i = blockIdx.x * 1024 + threadIdx.x;
    int c = (i < N_NODES) ? d_cursor[i] : 0;
    int s = block_incl_scan(c, smem);
    if (threadIdx.x == 1023) d_bsum[blockIdx.x] = s;
}

__global__ void scan2_kernel(int nblocks) {
    __shared__ int smem[32];
    int t = threadIdx.x;
    int v = (t < nblocks) ? d_bsum[t] : 0;
    int s = block_incl_scan(v, smem);
    if (t < nblocks) d_bsum[t] = s - v;  // exclusive
}

__global__ void scan3_kernel() {
    __shared__ int smem[32];
    int i = blockIdx.x * 1024 + threadIdx.x;
    int c = (i < N_NODES) ? d_cursor[i] : 0;
    int s = block_incl_scan(c, smem);
    int base = d_bsum[blockIdx.x];
    if (i < N_NODES) {
        int end = base + s;
        d_rowptr[i + 1] = end;
        d_cursor[i] = end - c;   // segment start; used as scatter cursor
    }
    if (i == 0) d_rowptr[0] = 0;
}

__global__ void scatter_kernel(const void* __restrict__ eidx,
                               const float* __restrict__ evals) {
    int e = blockIdx.x * blockDim.x + threadIdx.x;
    if (e < N_EDGES) {
        int r = edge_at(eidx, (size_t)e);
        int c = edge_at(eidx, (size_t)N_EDGES + e);
        if ((unsigned)r >= (unsigned)N_NODES) return;
        if ((unsigned)c >= (unsigned)N_NODES) c = 0;
        int p = atomicAdd(&d_cursor[r], 1);
        if ((unsigned)p < (unsigned)N_EDGES) {
            d_colidx[p] = c;
            d_eval[p]   = evals[e];
        }
    }
}

// ---------------- GEMM: H[m,n] = sum_k X[m,k] * W[n,k] + b[n] ----------------
// BM=128, BN=128, BK=16; 256 threads; 8 rows x 4 col-pairs per thread,
// packed f32x2 accumulators (no per-op pack/unpack movs).
__global__ __launch_bounds__(256, 2)
void gemm_kernel(const float* __restrict__ A, const float* __restrict__ W,
                 const float* __restrict__ bias) {
    __shared__ float sA[16][132];
    __shared__ float sB[16][132];
    const int tid = threadIdx.x;
    const int m0 = blockIdx.y * 128;
    const int n0 = blockIdx.x * 128;
    const int tn = tid & 15;        // 16 col-threads
    const int tm = tid >> 4;        // 16 row-threads

    // acc[i][j]: row tm*8+i, column pair (2*tn + 32*j, +1)
    u64 acc[8][4];
#pragma unroll
    for (int i = 0; i < 8; i++)
#pragma unroll
        for (int j = 0; j < 4; j++) acc[i][j] = 0ull;

    const int r0  = tid >> 2;          // 0..63
    const int kq0 = (tid & 3) * 4;     // 0,4,8,12
    int rowA0 = m0 + r0;      if (rowA0 > N_NODES - 1) rowA0 = N_NODES - 1;
    int rowA1 = m0 + r0 + 64; if (rowA1 > N_NODES - 1) rowA1 = N_NODES - 1;
    const float* a0p = A + (size_t)rowA0 * N_FEAT + kq0;
    const float* a1p = A + (size_t)rowA1 * N_FEAT + kq0;
    const float* b0p = W + (size_t)(n0 + r0) * N_FEAT + kq0;
    const float* b1p = W + (size_t)(n0 + r0 + 64) * N_FEAT + kq0;

    for (int k0 = 0; k0 < N_FEAT; k0 += 16) {
        float4 va0 = *(const float4*)(a0p + k0);
        float4 va1 = *(const float4*)(a1p + k0);
        float4 vb0 = *(const float4*)(b0p + k0);
        float4 vb1 = *(const float4*)(b1p + k0);
        __syncthreads();
        sA[kq0 + 0][r0] = va0.x; sA[kq0 + 1][r0] = va0.y;
        sA[kq0 + 2][r0] = va0.z; sA[kq0 + 3][r0] = va0.w;
        sA[kq0 + 0][r0 + 64] = va1.x; sA[kq0 + 1][r0 + 64] = va1.y;
        sA[kq0 + 2][r0 + 64] = va1.z; sA[kq0 + 3][r0 + 64] = va1.w;
        sB[kq0 + 0][r0] = vb0.x; sB[kq0 + 1][r0] = vb0.y;
        sB[kq0 + 2][r0] = vb0.z; sB[kq0 + 3][r0] = vb0.w;
        sB[kq0 + 0][r0 + 64] = vb1.x; sB[kq0 + 1][r0 + 64] = vb1.y;
        sB[kq0 + 2][r0 + 64] = vb1.z; sB[kq0 + 3][r0 + 64] = vb1.w;
        __syncthreads();
#pragma unroll
        for (int kk = 0; kk < 16; kk++) {
            // B pairs: u64 at pair index tn + 16j -> columns (2tn+32j, 2tn+32j+1)
            const u64* brow = (const u64*)&sB[kk][0];
            u64 b0 = brow[tn];
            u64 b1 = brow[tn + 16];
            u64 b2 = brow[tn + 32];
            u64 b3 = brow[tn + 48];
            float4 a0v = *(const float4*)&sA[kk][tm * 8];
            float4 a1v = *(const float4*)&sA[kk][tm * 8 + 4];
            float av[8] = {a0v.x, a0v.y, a0v.z, a0v.w, a1v.x, a1v.y, a1v.z, a1v.w};
#pragma unroll
            for (int i = 0; i < 8; i++) {
                u64 as = splat2(av[i]);
                fma2(acc[i][0], as, b0);
                fma2(acc[i][1], as, b1);
                fma2(acc[i][2], as, b2);
                fma2(acc[i][3], as, b3);
            }
        }
    }

    // epilogue: thread columns n0 + 2tn + 32j (pairs)
    float2 bp[4];
#pragma unroll
    for (int j = 0; j < 4; j++)
        bp[j] = *(const float2*)&bias[n0 + 2 * tn + 32 * j];
#pragma unroll
    for (int i = 0; i < 8; i++) {
        int gm = m0 + tm * 8 + i;
        if (gm < N_NODES) {
#pragma unroll
            for (int j = 0; j < 4; j++) {
                float2 c = unpack2(acc[i][j]);
                c.x += bp[j].x; c.y += bp[j].y;
                *(float2*)&d_h[(size_t)gm * N_HID + n0 + 2 * tn + 32 * j] = c;
            }
        }
    }
}

// ---------------- SpMM + PReLU: g[n,:] = prelu(sum_e w_e * h[col_e,:]) ----------------
__global__ __launch_bounds__(256)
void spmm_kernel(const float* __restrict__ prelu_a) {
    const int node = blockIdx.x;
    const int j = threadIdx.x;
    const int beg = d_rowptr[node];
    const int end = d_rowptr[node + 1];
    float acc = 0.f;
    int e = beg;
    for (; e + 4 <= end; e += 4) {
        int c0 = d_colidx[e], c1 = d_colidx[e + 1];
        int c2 = d_colidx[e + 2], c3 = d_colidx[e + 3];
        float w0 = d_eval[e], w1 = d_eval[e + 1];
        float w2 = d_eval[e + 2], w3 = d_eval[e + 3];
        float v0 = d_h[(size_t)c0 * N_HID + j];
        float v1 = d_h[(size_t)c1 * N_HID + j];
        float v2 = d_h[(size_t)c2 * N_HID + j];
        float v3 = d_h[(size_t)c3 * N_HID + j];
        acc += w0 * v0; acc += w1 * v1; acc += w2 * v2; acc += w3 * v3;
    }
    for (; e < end; ++e)
        acc += d_eval[e] * d_h[(size_t)d_colidx[e] * N_HID + j];
    float a0 = prelu_a[0];
    acc = (acc >= 0.f) ? acc : a0 * acc;
    d_g[(size_t)node * N_HID + j] = acc;
}

// ---------------- column sum of g (for mean over nodes) ----------------
__global__ void colsum_kernel() {
    const int j = threadIdx.x;
    const int start = blockIdx.x * 512;
    int stop = start + 512;
    if (stop > N_NODES) stop = N_NODES;
    float s = 0.f;
    for (int n = start; n < stop; n++) s += d_g[(size_t)n * N_HID + j];
    atomicAdd(&d_colsum[j], s);
}

// ---------------- v = bil_w @ sigmoid(mean) ----------------
__global__ void vker(const float* __restrict__ bw) {
    __shared__ float ssig[N_HID];
    int t = threadIdx.x;
    ssig[t] = 1.f / (1.f + expf(-d_colsum[t] * (1.f / (float)N_NODES)));
    __syncthreads();
    float acc = 0.f;
#pragma unroll 8
    for (int g = 0; g < N_HID; g++) acc += bw[t * N_HID + g] * ssig[g];
    d_v[t] = acc;
}

// ---------------- score[n] = dot(g[n], v) + bil_b ----------------
__global__ __launch_bounds__(256)
void score_kernel(const float* __restrict__ bb, float* __restrict__ out) {
    const int warp = threadIdx.x >> 5;
    const int lane = threadIdx.x & 31;
    const int node = blockIdx.x * 8 + warp;
    if (node >= N_NODES) return;
    const float4* gr = (const float4*)&d_g[(size_t)node * N_HID];
    const float4* vv = (const float4*)d_v;
    float acc = 0.f;
#pragma unroll
    for (int i = lane; i < 64; i += 32) {
        float4 a = gr[i];
        float4 b = vv[i];
        acc += a.x * b.x + a.y * b.y + a.z * b.z + a.w * b.w;
    }
#pragma unroll
    for (int o = 16; o > 0; o >>= 1) acc += __shfl_xor_sync(0xffffffffu, acc, o);
    if (lane == 0) out[node] = acc + bb[0];
}

// ---------------- launch ----------------
extern "C" void kernel_launch(void* const* d_in, const int* in_sizes, int n_in,
                              void* d_out, int out_size) {
    const float* x1  = (const float*)d_in[0];
    const float* x2  = (const float*)d_in[1];
    const float* ev  = (const float*)d_in[2];
    const float* fcw = (const float*)d_in[3];
    const float* fcb = (const float*)d_in[4];
    const float* pa  = (const float*)d_in[5];
    const float* bw  = (const float*)d_in[6];
    const float* bb  = (const float*)d_in[7];
    const void*  ei  = (const void*)d_in[8];
    float* out = (float*)d_out;

    const int scan_blocks = (N_NODES + 1023) / 1024;   // 98
    const int edge_blocks = (N_EDGES + 255) / 256;     // 12500

    // CSR build (per call; part of timed work)
    detect_kernel<<<1, 32>>>(ei);
    zero_kernel<<<(N_NODES + 255) / 256, 256>>>();
    hist_kernel<<<edge_blocks, 256>>>(ei);
    scan1_kernel<<<scan_blocks, 1024>>>();
    scan2_kernel<<<1, 128>>>(scan_blocks);
    scan3_kernel<<<scan_blocks, 1024>>>();
    scatter_kernel<<<edge_blocks, 256>>>(ei, ev);

    dim3 ggrid(2, (N_NODES + 127) / 128);

    // graph 1
    gemm_kernel<<<ggrid, 256>>>(x1, fcw, fcb);
    spmm_kernel<<<N_NODES, 256>>>(pa);
    colsum_kernel<<<(N_NODES + 511) / 512, 256>>>();
    vker<<<1, N_HID>>>(bw);
    score_kernel<<<(N_NODES + 7) / 8, 256>>>(bb, out);

    // graph 2 (reuses d_h/d_g; v already fixed)
    gemm_kernel<<<ggrid, 256>>>(x2, fcw, fcb);
    spmm_kernel<<<N_NODES, 256>>>(pa);
    score_kernel<<<(N_NODES + 7) / 8, 256>>>(bb, out + N_NODES);
}

// round 10
// speedup vs baseline: 1.8244x; 1.1477x over previous
#include <cuda_runtime.h>
#include <cuda_fp16.h>
#include <cstdint>

#define N_NODES 100000
#define N_EDGES 3200000
#define N_FEAT  512
#define N_HID   256

typedef unsigned long long u64;

// ---------------- static scratch (no allocation allowed) ----------------
__device__ float d_h[(size_t)N_NODES * N_HID];     // FC output
__device__ float d_g[(size_t)N_NODES * N_HID];     // post-SpMM/PReLU
__device__ int   d_rowptr[N_NODES + 1];
__device__ int   d_cursor[N_NODES];
__device__ int   d_colidx[N_EDGES];
__device__ float d_eval[N_EDGES];
__device__ int   d_bsum[128];
__device__ float d_colsum[N_HID];
__device__ float d_v[N_HID];
__device__ int   d_is32;
// A as fp16 hi/lo, pair-permuted, [N_NODES][256] u32 (2 fp16 per u32)
__device__ uint32_t d_ah[(size_t)N_NODES * (N_FEAT / 2)];
__device__ uint32_t d_al[(size_t)N_NODES * (N_FEAT / 2)];
// W as fp16 hi/lo, pair-permuted, [N_HID][256] u32
__device__ uint32_t d_whp[N_HID * (N_FEAT / 2)];
__device__ uint32_t d_wlp[N_HID * (N_FEAT / 2)];

// ---------------- helpers ----------------
__device__ __forceinline__ uint32_t smem_u32p(const void* p) {
    uint32_t a;
    asm("{ .reg .u64 t; cvta.to.shared.u64 t, %1; cvt.u32.u64 %0, t; }" : "=r"(a) : "l"(p));
    return a;
}
__device__ __forceinline__ void cpa16(uint32_t dst, const void* src) {
    asm volatile("cp.async.cg.shared.global [%0], [%1], 16;" :: "r"(dst), "l"(src));
}
__device__ __forceinline__ void cpa_commit() {
    asm volatile("cp.async.commit_group;" ::: "memory");
}
__device__ __forceinline__ void mma_f16(float* c, const uint32_t* a, const uint32_t* b) {
    asm volatile("mma.sync.aligned.m16n8k16.row.col.f32.f16.f16.f32 "
        "{%0,%1,%2,%3}, {%4,%5,%6,%7}, {%8,%9}, {%0,%1,%2,%3};"
        : "+f"(c[0]), "+f"(c[1]), "+f"(c[2]), "+f"(c[3])
        : "r"(a[0]), "r"(a[1]), "r"(a[2]), "r"(a[3]), "r"(b[0]), "r"(b[1]));
}

__device__ __forceinline__ int warp_incl_scan(int v) {
    int lane = threadIdx.x & 31;
#pragma unroll
    for (int o = 1; o < 32; o <<= 1) {
        int t = __shfl_up_sync(0xffffffffu, v, o);
        if (lane >= o) v += t;
    }
    return v;
}
__device__ __forceinline__ int block_incl_scan(int v, int* smem) {
    int lane = threadIdx.x & 31;
    int wid  = threadIdx.x >> 5;
    int nw   = blockDim.x >> 5;
    int s = warp_incl_scan(v);
    if (lane == 31) smem[wid] = s;
    __syncthreads();
    if (wid == 0) {
        int t = (lane < nw) ? smem[lane] : 0;
        t = warp_incl_scan(t);
        if (lane < nw) smem[lane] = t;
    }
    __syncthreads();
    int add = (wid > 0) ? smem[wid - 1] : 0;
    return s + add;
}
__device__ __forceinline__ int edge_at(const void* eidx, size_t idx) {
    if (d_is32) return ((const int*)eidx)[idx];
    return (int)((const long long*)eidx)[idx];
}

// ---------------- dtype detection ----------------
__global__ void detect_kernel(const void* eidx) {
    if (threadIdx.x == 0 && blockIdx.x == 0) {
        const long long* p = (const long long*)eidx;
        int is32 = 0;
        for (int i = 0; i < 64; i++) {
            long long v = p[i];
            if (v < 0 || v >= (long long)N_NODES) { is32 = 1; break; }
        }
        d_is32 = is32;
    }
}

// ---------------- fp32 -> fp16 hi/lo with pair permutation ----------------
// Each thread handles one k16 group (16 floats = 8 pairs). Output order
// within group: {p0,p4,p1,p5, p2,p6,p3,p7} so fragment (p, p+4) is one u64.
__device__ __forceinline__ void cvt_group(const float* src, uint32_t* hp, uint32_t* lp) {
    float v[16];
#pragma unroll
    for (int i = 0; i < 4; i++) {
        float4 t = ((const float4*)src)[i];
        v[4 * i] = t.x; v[4 * i + 1] = t.y; v[4 * i + 2] = t.z; v[4 * i + 3] = t.w;
    }
#pragma unroll
    for (int p = 0; p < 8; p++) {
        __half h0 = __float2half_rn(v[2 * p]);
        __half h1 = __float2half_rn(v[2 * p + 1]);
        float r0 = v[2 * p] - __half2float(h0);
        float r1 = v[2 * p + 1] - __half2float(h1);
        __half l0 = __float2half_rn(r0);
        __half l1 = __float2half_rn(r1);
        hp[p] = (uint32_t)__half_as_ushort(h0) | ((uint32_t)__half_as_ushort(h1) << 16);
        lp[p] = (uint32_t)__half_as_ushort(l0) | ((uint32_t)__half_as_ushort(l1) << 16);
    }
}
__global__ void acvt_kernel(const float* __restrict__ A) {
    int gid = blockIdx.x * blockDim.x + threadIdx.x;
    if (gid >= N_NODES * (N_FEAT / 16)) return;
    uint32_t hp[8], lp[8];
    cvt_group(A + (size_t)gid * 16, hp, lp);
    uint4* dh = (uint4*)d_ah + (size_t)gid * 2;
    uint4* dl = (uint4*)d_al + (size_t)gid * 2;
    dh[0] = make_uint4(hp[0], hp[4], hp[1], hp[5]);
    dh[1] = make_uint4(hp[2], hp[6], hp[3], hp[7]);
    dl[0] = make_uint4(lp[0], lp[4], lp[1], lp[5]);
    dl[1] = make_uint4(lp[2], lp[6], lp[3], lp[7]);
}
__global__ void wcvt_kernel(const float* __restrict__ W) {
    int gid = blockIdx.x * blockDim.x + threadIdx.x;
    if (gid >= N_HID * (N_FEAT / 16)) return;
    uint32_t hp[8], lp[8];
    cvt_group(W + (size_t)gid * 16, hp, lp);
    uint4* dh = (uint4*)d_whp + (size_t)gid * 2;
    uint4* dl = (uint4*)d_wlp + (size_t)gid * 2;
    dh[0] = make_uint4(hp[0], hp[4], hp[1], hp[5]);
    dh[1] = make_uint4(hp[2], hp[6], hp[3], hp[7]);
    dl[0] = make_uint4(lp[0], lp[4], lp[1], lp[5]);
    dl[1] = make_uint4(lp[2], lp[6], lp[3], lp[7]);
}

// ---------------- graph build ----------------
__global__ void zero_kernel() {
    int i = blockIdx.x * blockDim.x + threadIdx.x;
    if (i < N_NODES) d_cursor[i] = 0;
    if (i < N_HID)   d_colsum[i] = 0.f;
}
__global__ void hist_kernel(const void* __restrict__ eidx) {
    int e = blockIdx.x * blockDim.x + threadIdx.x;
    if (e < N_EDGES) {
        int r = edge_at(eidx, (size_t)e);
        if ((unsigned)r < (unsigned)N_NODES)
            atomicAdd(&d_cursor[r], 1);
    }
}
__global__ void scan1_kernel() {
    __shared__ int smem[32];
    int i = blockIdx.x * 1024 + threadIdx.x;
    int c = (i < N_NODES) ? d_cursor[i] : 0;
    int s = block_incl_scan(c, smem);
    if (threadIdx.x == 1023) d_bsum[blockIdx.x] = s;
}
__global__ void scan2_kernel(int nblocks) {
    __shared__ int smem[32];
    int t = threadIdx.x;
    int v = (t < nblocks) ? d_bsum[t] : 0;
    int s = block_incl_scan(v, smem);
    if (t < nblocks) d_bsum[t] = s - v;  // exclusive
}
__global__ void scan3_kernel() {
    __shared__ int smem[32];
    int i = blockIdx.x * 1024 + threadIdx.x;
    int c = (i < N_NODES) ? d_cursor[i] : 0;
    int s = block_incl_scan(c, smem);
    int base = d_bsum[blockIdx.x];
    if (i < N_NODES) {
        int end = base + s;
        d_rowptr[i + 1] = end;
        d_cursor[i] = end - c;
    }
    if (i == 0) d_rowptr[0] = 0;
}
__global__ void scatter_kernel(const void* __restrict__ eidx,
                               const float* __restrict__ evals) {
    int e = blockIdx.x * blockDim.x + threadIdx.x;
    if (e < N_EDGES) {
        int r = edge_at(eidx, (size_t)e);
        int c = edge_at(eidx, (size_t)N_EDGES + e);
        if ((unsigned)r >= (unsigned)N_NODES) return;
        if ((unsigned)c >= (unsigned)N_NODES) c = 0;
        int p = atomicAdd(&d_cursor[r], 1);
        if ((unsigned)p < (unsigned)N_EDGES) {
            d_colidx[p] = c;
            d_eval[p]   = evals[e];
        }
    }
}

// ---------------- GEMM: mma.sync f16 3-term split ----------------
// H[m,n] = sum_k A[m,k]*W[n,k] + b[n];  128x128 tile, BK=32, double-buffered.
// smem row stride 24 u32 (conflict-free LDS.64 fragments, 16B-aligned rows).
// smem u32 layout: AH[2][BUFU] AL[2][BUFU] BH[2][BUFU] BL[2][BUFU]
#define SROW 24
#define BUFU (128 * SROW)          // u32 per array per buffer = 3072
__global__ void __launch_bounds__(256, 1)
gemm_mma_kernel(const float* __restrict__ bias) {
    extern __shared__ uint32_t sm[];
    uint32_t* AH = sm;                 // [2][BUFU]
    uint32_t* AL = sm + 2 * BUFU;
    uint32_t* BH = sm + 4 * BUFU;
    uint32_t* BL = sm + 6 * BUFU;
    const uint32_t sbase = smem_u32p(sm);

    const int tid = threadIdx.x, lane = tid & 31, wid = tid >> 5;
    const int m0 = blockIdx.y * 128, n0 = blockIdx.x * 128;
    const int g = lane >> 2, tq = lane & 3;
    const int wm = (wid >> 1) * 32, wn = (wid & 1) * 64;

    // loader mapping: 2 threads per row, 8 u32 each
    const int lr = tid >> 1;
    const int lp = tid & 1;
    int arow = m0 + lr; if (arow >= N_NODES) arow = N_NODES - 1;
    const uint32_t* agh = d_ah + (size_t)arow * 256 + lp * 8;
    const uint32_t* agl = d_al + (size_t)arow * 256 + lp * 8;
    const uint32_t* bgh = d_whp + (size_t)(n0 + lr) * 256 + lp * 8;
    const uint32_t* bgl = d_wlp + (size_t)(n0 + lr) * 256 + lp * 8;
    const uint32_t sdst = (uint32_t)(lr * SROW + lp * 8) * 4;  // byte offset in buffer

    float acc[2][8][4];
#pragma unroll
    for (int mt = 0; mt < 2; mt++)
#pragma unroll
        for (int nt = 0; nt < 8; nt++)
#pragma unroll
            for (int c = 0; c < 4; c++) acc[mt][nt][c] = 0.f;

// byte offsets: AH buffer b at b*BUFU*4; AL at (2+b)*BUFU*4; BH at (4+b)*BUFU*4; BL at (6+b)*BUFU*4
#define PREFETCH(kc, b) do { \
    uint32_t o = sbase + (uint32_t)(b) * (BUFU * 4) + sdst; \
    const uint32_t ksrc = (uint32_t)(kc) * 16; \
    cpa16(o,                    agh + ksrc); cpa16(o + 16,                    agh + ksrc + 4); \
    cpa16(o + 2 * BUFU * 4,     agl + ksrc); cpa16(o + 2 * BUFU * 4 + 16,     agl + ksrc + 4); \
    cpa16(o + 4 * BUFU * 4,     bgh + ksrc); cpa16(o + 4 * BUFU * 4 + 16,     bgh + ksrc + 4); \
    cpa16(o + 6 * BUFU * 4,     bgl + ksrc); cpa16(o + 6 * BUFU * 4 + 16,     bgl + ksrc + 4); \
} while (0)

    PREFETCH(0, 0);
    cpa_commit();

    for (int kc = 0; kc < N_FEAT / 32; kc++) {
        if (kc < N_FEAT / 32 - 1) {
            PREFETCH(kc + 1, (kc + 1) & 1);
            cpa_commit();
            asm volatile("cp.async.wait_group 1;" ::: "memory");
        } else {
            asm volatile("cp.async.wait_group 0;" ::: "memory");
        }
        __syncthreads();

        const uint32_t bb = (uint32_t)(kc & 1) * BUFU;
#pragma unroll
        for (int kk = 0; kk < 2; kk++) {
            const int kb = kk * 8 + 2 * tq;
            uint32_t ah[2][4], al[2][4], bh[8][2], bl[8][2];
#pragma unroll
            for (int mt = 0; mt < 2; mt++) {
                int r = wm + mt * 16 + g;
                u64 t0 = *(const u64*)(AH + bb + r * SROW + kb);
                u64 t1 = *(const u64*)(AH + bb + (r + 8) * SROW + kb);
                ah[mt][0] = (uint32_t)t0; ah[mt][2] = (uint32_t)(t0 >> 32);
                ah[mt][1] = (uint32_t)t1; ah[mt][3] = (uint32_t)(t1 >> 32);
                u64 s0 = *(const u64*)(AL + bb + r * SROW + kb);
                u64 s1 = *(const u64*)(AL + bb + (r + 8) * SROW + kb);
                al[mt][0] = (uint32_t)s0; al[mt][2] = (uint32_t)(s0 >> 32);
                al[mt][1] = (uint32_t)s1; al[mt][3] = (uint32_t)(s1 >> 32);
            }
#pragma unroll
            for (int nt = 0; nt < 8; nt++) {
                int r = wn + nt * 8 + g;
                u64 t = *(const u64*)(BH + bb + r * SROW + kb);
                bh[nt][0] = (uint32_t)t; bh[nt][1] = (uint32_t)(t >> 32);
                u64 s = *(const u64*)(BL + bb + r * SROW + kb);
                bl[nt][0] = (uint32_t)s; bl[nt][1] = (uint32_t)(s >> 32);
            }
#pragma unroll
            for (int mt = 0; mt < 2; mt++)
#pragma unroll
                for (int nt = 0; nt < 8; nt++) {
                    mma_f16(acc[mt][nt], ah[mt], bh[nt]);
                    mma_f16(acc[mt][nt], al[mt], bh[nt]);
                    mma_f16(acc[mt][nt], ah[mt], bl[nt]);
                }
        }
        __syncthreads();
    }
#undef PREFETCH

    // epilogue
#pragma unroll
    for (int mt = 0; mt < 2; mt++) {
        int r0 = m0 + wm + mt * 16 + g;
        int r1 = r0 + 8;
#pragma unroll
        for (int nt = 0; nt < 8; nt++) {
            int col = n0 + wn + nt * 8 + 2 * tq;
            float2 b = *(const float2*)&bias[col];
            if (r0 < N_NODES) {
                float2 o = make_float2(acc[mt][nt][0] + b.x, acc[mt][nt][1] + b.y);
                *(float2*)&d_h[(size_t)r0 * N_HID + col] = o;
            }
            if (r1 < N_NODES) {
                float2 o = make_float2(acc[mt][nt][2] + b.x, acc[mt][nt][3] + b.y);
                *(float2*)&d_h[(size_t)r1 * N_HID + col] = o;
            }
        }
    }
}

// ---------------- SpMM + PReLU ----------------
__global__ __launch_bounds__(256)
void spmm_kernel(const float* __restrict__ prelu_a) {
    const int node = blockIdx.x;
    const int j = threadIdx.x;
    const int beg = d_rowptr[node];
    const int end = d_rowptr[node + 1];
    float acc = 0.f;
    int e = beg;
    for (; e + 4 <= end; e += 4) {
        int c0 = d_colidx[e], c1 = d_colidx[e + 1];
        int c2 = d_colidx[e + 2], c3 = d_colidx[e + 3];
        float w0 = d_eval[e], w1 = d_eval[e + 1];
        float w2 = d_eval[e + 2], w3 = d_eval[e + 3];
        float v0 = d_h[(size_t)c0 * N_HID + j];
        float v1 = d_h[(size_t)c1 * N_HID + j];
        float v2 = d_h[(size_t)c2 * N_HID + j];
        float v3 = d_h[(size_t)c3 * N_HID + j];
        acc += w0 * v0; acc += w1 * v1; acc += w2 * v2; acc += w3 * v3;
    }
    for (; e < end; ++e)
        acc += d_eval[e] * d_h[(size_t)d_colidx[e] * N_HID + j];
    float a0 = prelu_a[0];
    acc = (acc >= 0.f) ? acc : a0 * acc;
    d_g[(size_t)node * N_HID + j] = acc;
}

// ---------------- column sum / v / score ----------------
__global__ void colsum_kernel() {
    const int j = threadIdx.x;
    const int start = blockIdx.x * 512;
    int stop = start + 512;
    if (stop > N_NODES) stop = N_NODES;
    float s = 0.f;
    for (int n = start; n < stop; n++) s += d_g[(size_t)n * N_HID + j];
    atomicAdd(&d_colsum[j], s);
}
__global__ void vker(const float* __restrict__ bw) {
    __shared__ float ssig[N_HID];
    int t = threadIdx.x;
    ssig[t] = 1.f / (1.f + expf(-d_colsum[t] * (1.f / (float)N_NODES)));
    __syncthreads();
    float acc = 0.f;
#pragma unroll 8
    for (int g = 0; g < N_HID; g++) acc += bw[t * N_HID + g] * ssig[g];
    d_v[t] = acc;
}
__global__ __launch_bounds__(256)
void score_kernel(const float* __restrict__ bb, float* __restrict__ out) {
    const int warp = threadIdx.x >> 5;
    const int lane = threadIdx.x & 31;
    const int node = blockIdx.x * 8 + warp;
    if (node >= N_NODES) return;
    const float4* gr = (const float4*)&d_g[(size_t)node * N_HID];
    const float4* vv = (const float4*)d_v;
    float acc = 0.f;
#pragma unroll
    for (int i = lane; i < 64; i += 32) {
        float4 a = gr[i];
        float4 b = vv[i];
        acc += a.x * b.x + a.y * b.y + a.z * b.z + a.w * b.w;
    }
#pragma unroll
    for (int o = 16; o > 0; o >>= 1) acc += __shfl_xor_sync(0xffffffffu, acc, o);
    if (lane == 0) out[node] = acc + bb[0];
}

// ---------------- launch ----------------
extern "C" void kernel_launch(void* const* d_in, const int* in_sizes, int n_in,
                              void* d_out, int out_size) {
    const float* x1  = (const float*)d_in[0];
    const float* x2  = (const float*)d_in[1];
    const float* ev  = (const float*)d_in[2];
    const float* fcw = (const float*)d_in[3];
    const float* fcb = (const float*)d_in[4];
    const float* pa  = (const float*)d_in[5];
    const float* bw  = (const float*)d_in[6];
    const float* bb  = (const float*)d_in[7];
    const void*  ei  = (const void*)d_in[8];
    float* out = (float*)d_out;

    const int GEMM_SMEM = 8 * BUFU * 4;   // 98304 bytes
    static int smem_set = 0;
    if (!smem_set) {
        cudaFuncSetAttribute(gemm_mma_kernel,
                             cudaFuncAttributeMaxDynamicSharedMemorySize, GEMM_SMEM);
        smem_set = 1;
    }

    const int scan_blocks = (N_NODES + 1023) / 1024;   // 98
    const int edge_blocks = (N_EDGES + 255) / 256;     // 12500
    const int agrp_blocks = (N_NODES * (N_FEAT / 16) + 255) / 256;
    const int wgrp_blocks = (N_HID * (N_FEAT / 16) + 255) / 256;
    dim3 ggrid(N_HID / 128, (N_NODES + 127) / 128);    // (2, 782)

    // CSR build + W conversion
    detect_kernel<<<1, 32>>>(ei);
    wcvt_kernel<<<wgrp_blocks, 256>>>(fcw);
    zero_kernel<<<(N_NODES + 255) / 256, 256>>>();
    hist_kernel<<<edge_blocks, 256>>>(ei);
    scan1_kernel<<<scan_blocks, 1024>>>();
    scan2_kernel<<<1, 128>>>(scan_blocks);
    scan3_kernel<<<scan_blocks, 1024>>>();
    scatter_kernel<<<edge_blocks, 256>>>(ei, ev);

    // graph 1
    acvt_kernel<<<agrp_blocks, 256>>>(x1);
    gemm_mma_kernel<<<ggrid, 256, GEMM_SMEM>>>(fcb);
    spmm_kernel<<<N_NODES, 256>>>(pa);
    colsum_kernel<<<(N_NODES + 511) / 512, 256>>>();
    vker<<<1, N_HID>>>(bw);
    score_kernel<<<(N_NODES + 7) / 8, 256>>>(bb, out);

    // graph 2 (reuses d_ah/d_al)
    acvt_kernel<<<agrp_blocks, 256>>>(x2);
    gemm_mma_kernel<<<ggrid, 256, GEMM_SMEM>>>(fcb);
    spmm_kernel<<<N_NODES, 256>>>(pa);
    score_kernel<<<(N_NODES + 7) / 8, 256>>>(bb, out + N_NODES);
}

// round 12
// speedup vs baseline: 2.5685x; 1.4079x over previous
#include <cuda_runtime.h>
#include <cuda_fp16.h>
#include <cstdint>

#define N_NODES 100000
#define N_EDGES 3200000
#define N_FEAT  512
#define N_HID   256

typedef unsigned long long u64;

// ---------------- static scratch (no allocation allowed) ----------------
__device__ uint32_t d_hh[(size_t)N_NODES * (N_HID / 2)];   // FC output, fp16x2
__device__ float d_g[(size_t)N_NODES * N_HID];             // post-SpMM/PReLU
__device__ int   d_rowptr[N_NODES + 1];
__device__ int   d_cursor[N_NODES];
__device__ int   d_colidx[N_EDGES];
__device__ float d_eval[N_EDGES];
__device__ int   d_bsum[128];
__device__ float d_colsum[N_HID];
__device__ float d_v[N_HID];
__device__ int   d_is32;
// A as fp16 hi/lo, pair-permuted, [N_NODES][256] u32 (2 fp16 per u32)
__device__ uint32_t d_ah[(size_t)N_NODES * (N_FEAT / 2)];
__device__ uint32_t d_al[(size_t)N_NODES * (N_FEAT / 2)];
// W as fp16 hi/lo, pair-permuted, [N_HID][256] u32
__device__ uint32_t d_whp[N_HID * (N_FEAT / 2)];
__device__ uint32_t d_wlp[N_HID * (N_FEAT / 2)];

// ---------------- helpers ----------------
__device__ __forceinline__ uint32_t smem_u32p(const void* p) {
    uint32_t a;
    asm("{ .reg .u64 t; cvta.to.shared.u64 t, %1; cvt.u32.u64 %0, t; }" : "=r"(a) : "l"(p));
    return a;
}
__device__ __forceinline__ void cpa16(uint32_t dst, const void* src) {
    asm volatile("cp.async.cg.shared.global [%0], [%1], 16;" :: "r"(dst), "l"(src));
}
__device__ __forceinline__ void cpa_commit() {
    asm volatile("cp.async.commit_group;" ::: "memory");
}
__device__ __forceinline__ void mma_f16(float* c, const uint32_t* a, const uint32_t* b) {
    asm volatile("mma.sync.aligned.m16n8k16.row.col.f32.f16.f16.f32 "
        "{%0,%1,%2,%3}, {%4,%5,%6,%7}, {%8,%9}, {%0,%1,%2,%3};"
        : "+f"(c[0]), "+f"(c[1]), "+f"(c[2]), "+f"(c[3])
        : "r"(a[0]), "r"(a[1]), "r"(a[2]), "r"(a[3]), "r"(b[0]), "r"(b[1]));
}

__device__ __forceinline__ int warp_incl_scan(int v) {
    int lane = threadIdx.x & 31;
#pragma unroll
    for (int o = 1; o < 32; o <<= 1) {
        int t = __shfl_up_sync(0xffffffffu, v, o);
        if (lane >= o) v += t;
    }
    return v;
}
__device__ __forceinline__ int block_incl_scan(int v, int* smem) {
    int lane = threadIdx.x & 31;
    int wid  = threadIdx.x >> 5;
    int nw   = blockDim.x >> 5;
    int s = warp_incl_scan(v);
    if (lane == 31) smem[wid] = s;
    __syncthreads();
    if (wid == 0) {
        int t = (lane < nw) ? smem[lane] : 0;
        t = warp_incl_scan(t);
        if (lane < nw) smem[lane] = t;
    }
    __syncthreads();
    int add = (wid > 0) ? smem[wid - 1] : 0;
    return s + add;
}
__device__ __forceinline__ int edge_at(const void* eidx, size_t idx) {
    if (d_is32) return ((const int*)eidx)[idx];
    return (int)((const long long*)eidx)[idx];
}

// ---------------- dtype detection ----------------
__global__ void detect_kernel(const void* eidx) {
    if (threadIdx.x == 0 && blockIdx.x == 0) {
        const long long* p = (const long long*)eidx;
        int is32 = 0;
        for (int i = 0; i < 64; i++) {
            long long v = p[i];
            if (v < 0 || v >= (long long)N_NODES) { is32 = 1; break; }
        }
        d_is32 = is32;
    }
}

// ---------------- fp32 -> fp16 hi/lo with pair permutation ----------------
__device__ __forceinline__ void cvt_group(const float* src, uint32_t* hp, uint32_t* lp) {
    float v[16];
#pragma unroll
    for (int i = 0; i < 4; i++) {
        float4 t = ((const float4*)src)[i];
        v[4 * i] = t.x; v[4 * i + 1] = t.y; v[4 * i + 2] = t.z; v[4 * i + 3] = t.w;
    }
#pragma unroll
    for (int p = 0; p < 8; p++) {
        __half h0 = __float2half_rn(v[2 * p]);
        __half h1 = __float2half_rn(v[2 * p + 1]);
        float r0 = v[2 * p] - __half2float(h0);
        float r1 = v[2 * p + 1] - __half2float(h1);
        __half l0 = __float2half_rn(r0);
        __half l1 = __float2half_rn(r1);
        hp[p] = (uint32_t)__half_as_ushort(h0) | ((uint32_t)__half_as_ushort(h1) << 16);
        lp[p] = (uint32_t)__half_as_ushort(l0) | ((uint32_t)__half_as_ushort(l1) << 16);
    }
}
__global__ void acvt_kernel(const float* __restrict__ A) {
    int gid = blockIdx.x * blockDim.x + threadIdx.x;
    if (gid >= N_NODES * (N_FEAT / 16)) return;
    uint32_t hp[8], lp[8];
    cvt_group(A + (size_t)gid * 16, hp, lp);
    uint4* dh = (uint4*)d_ah + (size_t)gid * 2;
    uint4* dl = (uint4*)d_al + (size_t)gid * 2;
    dh[0] = make_uint4(hp[0], hp[4], hp[1], hp[5]);
    dh[1] = make_uint4(hp[2], hp[6], hp[3], hp[7]);
    dl[0] = make_uint4(lp[0], lp[4], lp[1], lp[5]);
    dl[1] = make_uint4(lp[2], lp[6], lp[3], lp[7]);
}
__global__ void wcvt_kernel(const float* __restrict__ W) {
    int gid = blockIdx.x * blockDim.x + threadIdx.x;
    if (gid >= N_HID * (N_FEAT / 16)) return;
    uint32_t hp[8], lp[8];
    cvt_group(W + (size_t)gid * 16, hp, lp);
    uint4* dh = (uint4*)d_whp + (size_t)gid * 2;
    uint4* dl = (uint4*)d_wlp + (size_t)gid * 2;
    dh[0] = make_uint4(hp[0], hp[4], hp[1], hp[5]);
    dh[1] = make_uint4(hp[2], hp[6], hp[3], hp[7]);
    dl[0] = make_uint4(lp[0], lp[4], lp[1], lp[5]);
    dl[1] = make_uint4(lp[2], lp[6], lp[3], lp[7]);
}

// ---------------- graph build ----------------
__global__ void zero_kernel() {
    int i = blockIdx.x * blockDim.x + threadIdx.x;
    if (i < N_NODES) d_cursor[i] = 0;
    if (i < N_HID)   d_colsum[i] = 0.f;
}
__global__ void hist_kernel(const void* __restrict__ eidx) {
    int e = blockIdx.x * blockDim.x + threadIdx.x;
    if (e < N_EDGES) {
        int r = edge_at(eidx, (size_t)e);
        if ((unsigned)r < (unsigned)N_NODES)
            atomicAdd(&d_cursor[r], 1);
    }
}
__global__ void scan1_kernel() {
    __shared__ int smem[32];
    int i = blockIdx.x * 1024 + threadIdx.x;
    int c = (i < N_NODES) ? d_cursor[i] : 0;
    int s = block_incl_scan(c, smem);
    if (threadIdx.x == 1023) d_bsum[blockIdx.x] = s;
}
__global__ void scan2_kernel(int nblocks) {
    __shared__ int smem[32];
    int t = threadIdx.x;
    int v = (t < nblocks) ? d_bsum[t] : 0;
    int s = block_incl_scan(v, smem);
    if (t < nblocks) d_bsum[t] = s - v;  // exclusive
}
__global__ void scan3_kernel() {
    __shared__ int smem[32];
    int i = blockIdx.x * 1024 + threadIdx.x;
    int c = (i < N_NODES) ? d_cursor[i] : 0;
    int s = block_incl_scan(c, smem);
    int base = d_bsum[blockIdx.x];
    if (i < N_NODES) {
        int end = base + s;
        d_rowptr[i + 1] = end;
        d_cursor[i] = end - c;
    }
    if (i == 0) d_rowptr[0] = 0;
}
__global__ void scatter_kernel(const void* __restrict__ eidx,
                               const float* __restrict__ evals) {
    int e = blockIdx.x * blockDim.x + threadIdx.x;
    if (e < N_EDGES) {
        int r = edge_at(eidx, (size_t)e);
        int c = edge_at(eidx, (size_t)N_EDGES + e);
        if ((unsigned)r >= (unsigned)N_NODES) return;
        if ((unsigned)c >= (unsigned)N_NODES) c = 0;
        int p = atomicAdd(&d_cursor[r], 1);
        if ((unsigned)p < (unsigned)N_EDGES) {
            d_colidx[p] = c;
            d_eval[p]   = evals[e];
        }
    }
}

// ---------------- GEMM: mma.sync f16 3-term split ----------------
#define SROW 24
#define BUFU (128 * SROW)
__global__ void __launch_bounds__(256, 1)
gemm_mma_kernel(const float* __restrict__ bias) {
    extern __shared__ uint32_t sm[];
    uint32_t* AH = sm;
    uint32_t* AL = sm + 2 * BUFU;
    uint32_t* BH = sm + 4 * BUFU;
    uint32_t* BL = sm + 6 * BUFU;
    const uint32_t sbase = smem_u32p(sm);

    const int tid = threadIdx.x, lane = tid & 31, wid = tid >> 5;
    const int m0 = blockIdx.y * 128, n0 = blockIdx.x * 128;
    const int g = lane >> 2, tq = lane & 3;
    const int wm = (wid >> 1) * 32, wn = (wid & 1) * 64;

    const int lr = tid >> 1;
    const int lp = tid & 1;
    int arow = m0 + lr; if (arow >= N_NODES) arow = N_NODES - 1;
    const uint32_t* agh = d_ah + (size_t)arow * 256 + lp * 8;
    const uint32_t* agl = d_al + (size_t)arow * 256 + lp * 8;
    const uint32_t* bgh = d_whp + (size_t)(n0 + lr) * 256 + lp * 8;
    const uint32_t* bgl = d_wlp + (size_t)(n0 + lr) * 256 + lp * 8;
    const uint32_t sdst = (uint32_t)(lr * SROW + lp * 8) * 4;

    float acc[2][8][4];
#pragma unroll
    for (int mt = 0; mt < 2; mt++)
#pragma unroll
        for (int nt = 0; nt < 8; nt++)
#pragma unroll
            for (int c = 0; c < 4; c++) acc[mt][nt][c] = 0.f;

#define PREFETCH(kc, b) do { \
    uint32_t o = sbase + (uint32_t)(b) * (BUFU * 4) + sdst; \
    const uint32_t ksrc = (uint32_t)(kc) * 16; \
    cpa16(o,                    agh + ksrc); cpa16(o + 16,                    agh + ksrc + 4); \
    cpa16(o + 2 * BUFU * 4,     agl + ksrc); cpa16(o + 2 * BUFU * 4 + 16,     agl + ksrc + 4); \
    cpa16(o + 4 * BUFU * 4,     bgh + ksrc); cpa16(o + 4 * BUFU * 4 + 16,     bgh + ksrc + 4); \
    cpa16(o + 6 * BUFU * 4,     bgl + ksrc); cpa16(o + 6 * BUFU * 4 + 16,     bgl + ksrc + 4); \
} while (0)

    PREFETCH(0, 0);
    cpa_commit();

    for (int kc = 0; kc < N_FEAT / 32; kc++) {
        if (kc < N_FEAT / 32 - 1) {
            PREFETCH(kc + 1, (kc + 1) & 1);
            cpa_commit();
            asm volatile("cp.async.wait_group 1;" ::: "memory");
        } else {
            asm volatile("cp.async.wait_group 0;" ::: "memory");
        }
        __syncthreads();

        const uint32_t bb = (uint32_t)(kc & 1) * BUFU;
#pragma unroll
        for (int kk = 0; kk < 2; kk++) {
            const int kb = kk * 8 + 2 * tq;
            uint32_t ah[2][4], al[2][4], bh[8][2], bl[8][2];
#pragma unroll
            for (int mt = 0; mt < 2; mt++) {
                int r = wm + mt * 16 + g;
                u64 t0 = *(const u64*)(AH + bb + r * SROW + kb);
                u64 t1 = *(const u64*)(AH + bb + (r + 8) * SROW + kb);
                ah[mt][0] = (uint32_t)t0; ah[mt][2] = (uint32_t)(t0 >> 32);
                ah[mt][1] = (uint32_t)t1; ah[mt][3] = (uint32_t)(t1 >> 32);
                u64 s0 = *(const u64*)(AL + bb + r * SROW + kb);
                u64 s1 = *(const u64*)(AL + bb + (r + 8) * SROW + kb);
                al[mt][0] = (uint32_t)s0; al[mt][2] = (uint32_t)(s0 >> 32);
                al[mt][1] = (uint32_t)s1; al[mt][3] = (uint32_t)(s1 >> 32);
            }
#pragma unroll
            for (int nt = 0; nt < 8; nt++) {
                int r = wn + nt * 8 + g;
                u64 t = *(const u64*)(BH + bb + r * SROW + kb);
                bh[nt][0] = (uint32_t)t; bh[nt][1] = (uint32_t)(t >> 32);
                u64 s = *(const u64*)(BL + bb + r * SROW + kb);
                bl[nt][0] = (uint32_t)s; bl[nt][1] = (uint32_t)(s >> 32);
            }
#pragma unroll
            for (int mt = 0; mt < 2; mt++)
#pragma unroll
                for (int nt = 0; nt < 8; nt++) {
                    mma_f16(acc[mt][nt], ah[mt], bh[nt]);
                    mma_f16(acc[mt][nt], al[mt], bh[nt]);
                    mma_f16(acc[mt][nt], ah[mt], bl[nt]);
                }
        }
        __syncthreads();
    }
#undef PREFETCH

    // epilogue: bias add then pack fp16x2 into d_hh
#pragma unroll
    for (int mt = 0; mt < 2; mt++) {
        int r0 = m0 + wm + mt * 16 + g;
        int r1 = r0 + 8;
#pragma unroll
        for (int nt = 0; nt < 8; nt++) {
            int col = n0 + wn + nt * 8 + 2 * tq;
            float2 b = *(const float2*)&bias[col];
            int pidx = col >> 1;   // u32 pair index within row
            if (r0 < N_NODES) {
                __half2 o = __floats2half2_rn(acc[mt][nt][0] + b.x, acc[mt][nt][1] + b.y);
                d_hh[(size_t)r0 * (N_HID / 2) + pidx] = *(uint32_t*)&o;
            }
            if (r1 < N_NODES) {
                __half2 o = __floats2half2_rn(acc[mt][nt][2] + b.x, acc[mt][nt][3] + b.y);
                d_hh[(size_t)r1 * (N_HID / 2) + pidx] = *(uint32_t*)&o;
            }
        }
    }
}

// ---------------- SpMM + PReLU (fp16 gather, fp32 accumulate) ----------------
// block = 128 threads; thread j handles column pair (2j, 2j+1)
__global__ __launch_bounds__(128)
void spmm_kernel(const float* __restrict__ prelu_a) {
    const int node = blockIdx.x;
    const int j = threadIdx.x;
    const int beg = d_rowptr[node];
    const int end = d_rowptr[node + 1];
    float ax = 0.f, ay = 0.f;
    int e = beg;
    for (; e + 4 <= end; e += 4) {
        int c0 = d_colidx[e], c1 = d_colidx[e + 1];
        int c2 = d_colidx[e + 2], c3 = d_colidx[e + 3];
        float w0 = d_eval[e], w1 = d_eval[e + 1];
        float w2 = d_eval[e + 2], w3 = d_eval[e + 3];
        uint32_t p0 = d_hh[(size_t)c0 * (N_HID / 2) + j];
        uint32_t p1 = d_hh[(size_t)c1 * (N_HID / 2) + j];
        uint32_t p2 = d_hh[(size_t)c2 * (N_HID / 2) + j];
        uint32_t p3 = d_hh[(size_t)c3 * (N_HID / 2) + j];
        float2 v0 = __half22float2(*(__half2*)&p0);
        float2 v1 = __half22float2(*(__half2*)&p1);
        float2 v2 = __half22float2(*(__half2*)&p2);
        float2 v3 = __half22float2(*(__half2*)&p3);
        ax += w0 * v0.x; ay += w0 * v0.y;
        ax += w1 * v1.x; ay += w1 * v1.y;
        ax += w2 * v2.x; ay += w2 * v2.y;
        ax += w3 * v3.x; ay += w3 * v3.y;
    }
    for (; e < end; ++e) {
        int c = d_colidx[e];
        float w = d_eval[e];
        uint32_t p = d_hh[(size_t)c * (N_HID / 2) + j];
        float2 v = __half22float2(*(__half2*)&p);
        ax += w * v.x; ay += w * v.y;
    }
    float a0 = prelu_a[0];
    ax = (ax >= 0.f) ? ax : a0 * ax;
    ay = (ay >= 0.f) ? ay : a0 * ay;
    *(float2*)&d_g[(size_t)node * N_HID + 2 * j] = make_float2(ax, ay);
}

// ---------------- column sum / v / score ----------------
__global__ void colsum_kernel() {
    const int j = threadIdx.x;
    const int start = blockIdx.x * 512;
    int stop = start + 512;
    if (stop > N_NODES) stop = N_NODES;
    float s = 0.f;
    for (int n = start; n < stop; n++) s += d_g[(size_t)n * N_HID + j];
    atomicAdd(&d_colsum[j], s);
}
__global__ void vker(const float* __restrict__ bw) {
    __shared__ float ssig[N_HID];
    int t = threadIdx.x;
    ssig[t] = 1.f / (1.f + expf(-d_colsum[t] * (1.f / (float)N_NODES)));
    __syncthreads();
    float acc = 0.f;
#pragma unroll 8
    for (int g = 0; g < N_HID; g++) acc += bw[t * N_HID + g] * ssig[g];
    d_v[t] = acc;
}
__global__ __launch_bounds__(256)
void score_kernel(const float* __restrict__ bb, float* __restrict__ out) {
    const int warp = threadIdx.x >> 5;
    const int lane = threadIdx.x & 31;
    const int node = blockIdx.x * 8 + warp;
    if (node >= N_NODES) return;
    const float4* gr = (const float4*)&d_g[(size_t)node * N_HID];
    const float4* vv = (const float4*)d_v;
    float acc = 0.f;
#pragma unroll
    for (int i = lane; i < 64; i += 32) {
        float4 a = gr[i];
        float4 b = vv[i];
        acc += a.x * b.x + a.y * b.y + a.z * b.z + a.w * b.w;
    }
#pragma unroll
    for (int o = 16; o > 0; o >>= 1) acc += __shfl_xor_sync(0xffffffffu, acc, o);
    if (lane == 0) out[node] = acc + bb[0];
}

// ---------------- launch ----------------
extern "C" void kernel_launch(void* const* d_in, const int* in_sizes, int n_in,
                              void* d_out, int out_size) {
    const float* x1  = (const float*)d_in[0];
    const float* x2  = (const float*)d_in[1];
    const float* ev  = (const float*)d_in[2];
    const float* fcw = (const float*)d_in[3];
    const float* fcb = (const float*)d_in[4];
    const float* pa  = (const float*)d_in[5];
    const float* bw  = (const float*)d_in[6];
    const float* bb  = (const float*)d_in[7];
    const void*  ei  = (const void*)d_in[8];
    float* out = (float*)d_out;

    const int GEMM_SMEM = 8 * BUFU * 4;   // 98304 bytes
    static int smem_set = 0;
    if (!smem_set) {
        cudaFuncSetAttribute(gemm_mma_kernel,
                             cudaFuncAttributeMaxDynamicSharedMemorySize, GEMM_SMEM);
        smem_set = 1;
    }

    const int scan_blocks = (N_NODES + 1023) / 1024;
    const int edge_blocks = (N_EDGES + 255) / 256;
    const int agrp_blocks = (N_NODES * (N_FEAT / 16) + 255) / 256;
    const int wgrp_blocks = (N_HID * (N_FEAT / 16) + 255) / 256;
    dim3 ggrid(N_HID / 128, (N_NODES + 127) / 128);

    // CSR build + W conversion
    detect_kernel<<<1, 32>>>(ei);
    wcvt_kernel<<<wgrp_blocks, 256>>>(fcw);
    zero_kernel<<<(N_NODES + 255) / 256, 256>>>();
    hist_kernel<<<edge_blocks, 256>>>(ei);
    scan1_kernel<<<scan_blocks, 1024>>>();
    scan2_kernel<<<1, 128>>>(scan_blocks);
    scan3_kernel<<<scan_blocks, 1024>>>();
    scatter_kernel<<<edge_blocks, 256>>>(ei, ev);

    // graph 1
    acvt_kernel<<<agrp_blocks, 256>>>(x1);
    gemm_mma_kernel<<<ggrid, 256, GEMM_SMEM>>>(fcb);
    spmm_kernel<<<N_NODES, 128>>>(pa);
    colsum_kernel<<<(N_NODES + 511) / 512, 256>>>();
    vker<<<1, N_HID>>>(bw);
    score_kernel<<<(N_NODES + 7) / 8, 256>>>(bb, out);

    // graph 2 (reuses d_ah/d_al/d_hh)
    acvt_kernel<<<agrp_blocks, 256>>>(x2);
    gemm_mma_kernel<<<ggrid, 256, GEMM_SMEM>>>(fcb);
    spmm_kernel<<<N_NODES, 128>>>(pa);
    score_kernel<<<(N_NODES + 7) / 8, 256>>>(bb, out + N_NODES);
}